// round 14
// baseline (speedup 1.0000x reference)
#include <cuda_runtime.h>

#define B_   128
#define NT   64
#define WIN  200
#define EMB  128

typedef unsigned long long ull;
#define NEG_INF (__int_as_float(0xff800000))

__device__ __forceinline__ ull fma2v(ull a, ull b, ull c) {
    ull d; asm("fma.rn.f32x2 %0, %1, %2, %3;" : "=l"(d) : "l"(a), "l"(b), "l"(c)); return d;
}
__device__ __forceinline__ ull pack2(float x, float y) {
    ull d; asm("mov.b64 %0, {%1, %2};" : "=l"(d) : "f"(x), "f"(y)); return d;
}
__device__ __forceinline__ float2 unpack2(ull a) {
    float2 r; asm("mov.b64 {%0, %1}, %2;" : "=f"(r.x), "=f"(r.y) : "l"(a)); return r;
}
// acc += relu2(hp + hq) * hw   (proven 4-instr form; scalar max on ALU pipe)
__device__ __forceinline__ void relu_dot2(ull& acc, ull hp, ull hq, ull hw) {
    asm("{\n\t"
        ".reg .b64 s;\n\t"
        ".reg .f32 lo, hi;\n\t"
        "add.rn.f32x2 s, %1, %2;\n\t"
        "mov.b64 {lo, hi}, s;\n\t"
        "max.f32 lo, lo, 0f00000000;\n\t"
        "max.f32 hi, hi, 0f00000000;\n\t"
        "mov.b64 s, {lo, hi};\n\t"
        "fma.rn.f32x2 %0, s, %3, %0;\n\t"
        "}" : "+l"(acc) : "l"(hp), "l"(hq), "l"(hw));
}

// global scratch (L2-resident)
__device__ float HQT[B_ * 32 * WIN * 4];   // n-chunked [b][32][200][4]
__device__ float HPg[B_ * NT * EMB];       // row-major [b*64+t][128]

// ===================== K1: projections, direct transposed store ============
#define K1_HQ_BLOCKS 800
#define K1_BLOCKS    1056

#define K1_X    0               /* [32][132] */
#define K1_WC   4224            /* [32][130] */
#define K1_ITM  8384            /* 32 ints   */
#define K1_FLOATS 8416
#define K1_BYTES (K1_FLOATS * 4)

__global__ void __launch_bounds__(256)
proj_kernel(const float* __restrict__ tvecs, const float* __restrict__ cvecs,
            const float* __restrict__ W_w, const float* __restrict__ W_b,
            const int* __restrict__ titems, const int* __restrict__ citems)
{
    extern __shared__ float sm[];
    float* X  = sm + K1_X;
    float* Wc = sm + K1_WC;
    int*  itm = (int*)(sm + K1_ITM);
    const int tid = threadIdx.x;
    const int warp = tid >> 5, lane = tid & 31;

    const bool is_hq = blockIdx.x < K1_HQ_BLOCKS;
    const int rbase = (is_hq ? blockIdx.x : (blockIdx.x - K1_HQ_BLOCKS)) * 32;
    const float* vecs = is_hq ? cvecs : tvecs;
    const int* items  = is_hq ? citems : titems;
    const int rowsper = is_hq ? WIN : NT;
    const int wcol    = is_hq ? EMB : 0;

    if (tid < 32) {
        int r = rbase + tid;
        itm[tid] = items[(r / rowsper) * rowsper + (r % rowsper)];
    }
    __syncthreads();

    // gather X rows [32][128] (pitch 132), coalesced per row
    for (int i = tid; i < 32 * 32; i += 256) {
        int row = i >> 5, c = i & 31;
        *(float4*)(X + row * 132 + c * 4) =
            *(const float4*)(vecs + (size_t)itm[row] * EMB + c * 4);
    }

    ull acc[4][2];
#pragma unroll
    for (int r = 0; r < 4; r++) { acc[r][0] = 0ull; acc[r][1] = 0ull; }

    for (int ec = 0; ec < 4; ++ec) {
        __syncthreads();
        for (int i = tid; i < 4096; i += 256) {
            int n = i >> 5, e = i & 31;
            Wc[e * 130 + n] = W_w[n * 256 + wcol + ec * 32 + e];
        }
        __syncthreads();
#pragma unroll
        for (int e4 = 0; e4 < 8; ++e4) {
            float4 xv[4];
#pragma unroll
            for (int r = 0; r < 4; r++)   // lane-uniform -> broadcast
                xv[r] = *(const float4*)(X + (warp * 4 + r) * 132 + ec * 32 + e4 * 4);
#pragma unroll
            for (int s = 0; s < 4; ++s) {
                int e = e4 * 4 + s;
                ull wa = *(const ull*)(Wc + e * 130 + 2 * lane);        // conflict-free
                ull wb = *(const ull*)(Wc + e * 130 + 64 + 2 * lane);   // conflict-free
#pragma unroll
                for (int r = 0; r < 4; r++) {
                    float x = (s == 0) ? xv[r].x : (s == 1) ? xv[r].y
                             : (s == 2) ? xv[r].z : xv[r].w;
                    ull xd = pack2(x, x);
                    acc[r][0] = fma2v(xd, wa, acc[r][0]);
                    acc[r][1] = fma2v(xd, wb, acc[r][1]);
                }
            }
        }
    }

    if (is_hq) {
        // +Wb and store straight to HQT from registers (no smem restage)
        float2 b0 = *(const float2*)(W_b + 2 * lane);
        float2 b1 = *(const float2*)(W_b + 64 + 2 * lane);
        const int ns0 = lane >> 1, off0 = (lane & 1) * 2;
#pragma unroll
        for (int r = 0; r < 4; r++) {
            int rg = rbase + warp * 4 + r;
            int bb = rg / WIN, ww = rg % WIN;
            float2 a0 = unpack2(acc[r][0]); a0.x += b0.x; a0.y += b0.y;
            float2 a1 = unpack2(acc[r][1]); a1.x += b1.x; a1.y += b1.y;
            float* base = HQT + (size_t)bb * 25600 + ww * 4 + off0;
            *(float2*)(base + ns0 * 800) = a0;
            *(float2*)(base + (16 + ns0) * 800) = a1;
        }
    } else {
#pragma unroll
        for (int r = 0; r < 4; r++) {
            int rg = rbase + warp * 4 + r;
            *(float2*)(HPg + (size_t)rg * EMB + 2 * lane) = unpack2(acc[r][0]);
            *(float2*)(HPg + (size_t)rg * EMB + 64 + 2 * lane) = unpack2(acc[r][1]);
        }
    }
}

// ===================== K2: relu-dot + softmax + AV =====================
// grid 512 = 128 b x 4 t-tiles(16); block 256 (8 warps)
#define K2_SHP   0
#define K2_SCR   0
#define K2_HW    8192
#define K2_ATT   8320           /* [16][224] */
#define K2_MADD  11904
#define K2_CI    12104
#define K2_MISC  12304          /* [0]=rnorm [1]=mask flag */
#define K2_FLOATS 12312
#define K2_BYTES (K2_FLOATS * 4)

__global__ void __launch_bounds__(256, 4)
att_kernel(const float* __restrict__ cvecs, const float* __restrict__ h_w,
           const int* __restrict__ citems, const unsigned char* __restrict__ mask,
           float* __restrict__ out)
{
    extern __shared__ float sm[];
    float* SHP  = sm + K2_SHP;
    float* SHW  = sm + K2_HW;
    float* ATT  = sm + K2_ATT;
    float* MADD = sm + K2_MADD;
    int*   CI   = (int*)(sm + K2_CI);
    const int tid = threadIdx.x;
    const int b  = blockIdx.x >> 2;
    const int t0 = (blockIdx.x & 3) * 16;
    const int warp = tid >> 5, lane = tid & 31;

    if (tid == 0) ((int*)sm)[K2_MISC + 1] = 0;
    __syncthreads();
    if (tid < 200) {
        unsigned w32 = ((const unsigned*)mask)[tid];
        if (w32 > 1u) ((int*)sm)[K2_MISC + 1] = 1;   // benign race
    }
    __syncthreads();
    {
        const bool bytes_layout = ((int*)sm)[K2_MISC + 1] != 0;
        if (tid < 200) {
            int mv = bytes_layout ? (int)mask[b * WIN + tid]
                                  : ((const int*)mask)[b * WIN + tid];
            MADD[tid] = mv ? NEG_INF : 0.0f;
            CI[tid] = citems[b * WIN + tid];
        }
        if (tid < 128) SHW[tid] = h_w[tid];
    }
    for (int i = tid; i < 16 * 32; i += 256) {
        int t = i >> 5, c = i & 31;
        *(float4*)(SHP + t * 132 + c * 4) =
            *(const float4*)(HPg + ((size_t)(b * NT + t0 + t)) * EMB + c * 4);
    }
    __syncthreads();
    if (tid < 32) {  // rnorm
        float c = 0.0f;
        for (int w = tid; w < WIN; w += 32) c += (MADD[w] < 0.0f) ? 1.0f : 0.0f;
#pragma unroll
        for (int o = 16; o; o >>= 1) c += __shfl_xor_sync(0xffffffffu, c, o);
        if (tid == 0) sm[K2_MISC] = 1.0f / sqrtf(1000.0f - c);
    }

    // ---- att: thread owns w; two passes of 8 t; explicit hq prefetch ----
    {
        const int w = tid;
        const bool act = (w < WIN);
        const float* hqp = HQT + (size_t)b * 25600 + (act ? w : 0) * 4;
#pragma unroll
        for (int th = 0; th < 2; ++th) {
            const float* shp = SHP + th * 8 * 132;
            ull acc[8];
#pragma unroll
            for (int t = 0; t < 8; ++t) acc[t] = 0ull;
            ulonglong2 hq = *(const ulonglong2*)(hqp);
#pragma unroll 4
            for (int ns = 0; ns < 32; ++ns) {
                ulonglong2 hq_next;
                if (ns < 31) hq_next = *(const ulonglong2*)(hqp + (ns + 1) * 800);
                ulonglong2 hw = *(const ulonglong2*)(SHW + ns * 4);
#pragma unroll
                for (int t = 0; t < 8; ++t) {
                    ulonglong2 p = *(const ulonglong2*)(shp + t * 132 + ns * 4);
                    relu_dot2(acc[t], p.x, hq.x, hw.x);
                    relu_dot2(acc[t], p.y, hq.y, hw.y);
                }
                if (ns < 31) hq = hq_next;
            }
            if (act) {
#pragma unroll
                for (int t = 0; t < 8; ++t) {
                    float2 a = unpack2(acc[t]);
                    ATT[(th * 8 + t) * 224 + w] = a.x + a.y;
                }
            }
        }
    }
    __syncthreads();

    // ---- softmax over w per t (8 warps x 2t) ----
    for (int t = warp; t < 16; t += 8) {
        float v[7], p[7];
        float m = NEG_INF;
#pragma unroll
        for (int k = 0; k < 7; k++) {
            int w = lane + 32 * k;
            v[k] = (w < WIN) ? (ATT[t * 224 + w] + MADD[w]) : NEG_INF;
            m = fmaxf(m, v[k]);
        }
#pragma unroll
        for (int o = 16; o; o >>= 1) m = fmaxf(m, __shfl_xor_sync(0xffffffffu, m, o));
        float s = 0.0f;
#pragma unroll
        for (int k = 0; k < 7; k++) { p[k] = __expf(v[k] - m); s += p[k]; }
#pragma unroll
        for (int o = 16; o; o >>= 1) s += __shfl_xor_sync(0xffffffffu, s, o);
        float inv = 1.0f / s;
#pragma unroll
        for (int k = 0; k < 7; k++) {
            int w = lane + 32 * k;
            if (w < WIN) ATT[t * 224 + w] = p[k] * inv;
        }
    }
    __syncthreads();   // ATT final; SHP dead -> scratch reuse safe

    // ---- AV: warp = (t-half, w-quarter); kv prefetch; partials in smem ----
    {
        const int th = warp & 1, wg = warp >> 1;
        float* SCR = sm + K2_SCR;
        ull acc[8][2];
#pragma unroll
        for (int t8 = 0; t8 < 8; ++t8) { acc[t8][0] = 0ull; acc[t8][1] = 0ull; }
        ulonglong2 kv = *(const ulonglong2*)(cvecs + (size_t)CI[wg * 50] * EMB + lane * 4);
#pragma unroll 2
        for (int wi = 0; wi < 50; ++wi) {
            int w = wg * 50 + wi;
            ulonglong2 kv_next;
            if (wi < 49)
                kv_next = *(const ulonglong2*)(cvecs + (size_t)CI[w + 1] * EMB + lane * 4);
#pragma unroll
            for (int t8 = 0; t8 < 8; ++t8) {
                float x = ATT[(th * 8 + t8) * 224 + w];   // broadcast
                ull d = pack2(x, x);
                acc[t8][0] = fma2v(d, kv.x, acc[t8][0]);
                acc[t8][1] = fma2v(d, kv.y, acc[t8][1]);
            }
            if (wi < 49) kv = kv_next;
        }
#pragma unroll
        for (int t8 = 0; t8 < 8; ++t8) {
            ulonglong2 v; v.x = acc[t8][0]; v.y = acc[t8][1];
            *(ulonglong2*)(SCR + (size_t)(warp * 8 + t8) * 128 + lane * 4) = v;
        }
    }
    __syncthreads();

    // ---- reduce 4 partials + scale + store ----
    {
        const float rn = sm[K2_MISC];
        for (int i = tid; i < 16 * 128; i += 256) {
            int t = i >> 7, e = i & 127;
            int th = t >> 3, t8 = t & 7;
            float s = 0.0f;
#pragma unroll
            for (int wg = 0; wg < 4; ++wg)
                s += sm[K2_SCR + (size_t)((wg * 2 + th) * 8 + t8) * 128 + e];
            out[(size_t)(b * NT + t0 + t) * EMB + e] = s * rn;
        }
    }
}

extern "C" void kernel_launch(void* const* d_in, const int* in_sizes, int n_in,
                              void* d_out, int out_size)
{
    const float* tvecs = (const float*)d_in[0];
    const float* cvecs = (const float*)d_in[1];
    const float* W_w   = (const float*)d_in[2];
    const float* W_b   = (const float*)d_in[3];
    const float* h_w   = (const float*)d_in[4];
    const int*   ti    = (const int*)d_in[6];
    const int*   ci    = (const int*)d_in[7];
    const unsigned char* mask = (const unsigned char*)d_in[8];

    cudaFuncSetAttribute(proj_kernel, cudaFuncAttributeMaxDynamicSharedMemorySize, K1_BYTES);
    cudaFuncSetAttribute(att_kernel,  cudaFuncAttributeMaxDynamicSharedMemorySize, K2_BYTES);
    proj_kernel<<<K1_BLOCKS, 256, K1_BYTES>>>(tvecs, cvecs, W_w, W_b, ti, ci);
    att_kernel<<<B_ * 4, 256, K2_BYTES>>>(cvecs, h_w, ci, mask, (float*)d_out);
}

// round 15
// speedup vs baseline: 1.0807x; 1.0807x over previous
#include <cuda_runtime.h>

#define B_   128
#define NT   64
#define WIN  200
#define EMB  128

typedef unsigned long long ull;
#define NEG_INF (__int_as_float(0xff800000))

__device__ __forceinline__ ull fma2v(ull a, ull b, ull c) {
    ull d; asm("fma.rn.f32x2 %0, %1, %2, %3;" : "=l"(d) : "l"(a), "l"(b), "l"(c)); return d;
}
__device__ __forceinline__ ull pack2(float x, float y) {
    ull d; asm("mov.b64 %0, {%1, %2};" : "=l"(d) : "f"(x), "f"(y)); return d;
}
__device__ __forceinline__ float2 unpack2(ull a) {
    float2 r; asm("mov.b64 {%0, %1}, %2;" : "=f"(r.x), "=f"(r.y) : "l"(a)); return r;
}
__device__ __forceinline__ void relu_dot2(ull& acc, ull hp, ull hq, ull hw) {
    asm("{\n\t"
        ".reg .b64 s;\n\t"
        ".reg .f32 lo, hi;\n\t"
        "add.rn.f32x2 s, %1, %2;\n\t"
        "mov.b64 {lo, hi}, s;\n\t"
        "max.f32 lo, lo, 0f00000000;\n\t"
        "max.f32 hi, hi, 0f00000000;\n\t"
        "mov.b64 s, {lo, hi};\n\t"
        "fma.rn.f32x2 %0, s, %3, %0;\n\t"
        "}" : "+l"(acc) : "l"(hp), "l"(hq), "l"(hw));
}

// global scratch (L2-resident)
__device__ float HQT[B_ * 32 * WIN * 4];   // n-chunked [b][32][200][4]
__device__ float HPg[B_ * NT * EMB];       // row-major [b*64+t][128]

// ===================== K1: projections (unchanged from R14) ================
#define K1_HQ_BLOCKS 800
#define K1_BLOCKS    1056

#define K1_X    0               /* [32][132] */
#define K1_WC   4224            /* [32][130] */
#define K1_ITM  8384            /* 32 ints   */
#define K1_FLOATS 8416
#define K1_BYTES (K1_FLOATS * 4)

__global__ void __launch_bounds__(256)
proj_kernel(const float* __restrict__ tvecs, const float* __restrict__ cvecs,
            const float* __restrict__ W_w, const float* __restrict__ W_b,
            const int* __restrict__ titems, const int* __restrict__ citems)
{
    extern __shared__ float sm[];
    float* X  = sm + K1_X;
    float* Wc = sm + K1_WC;
    int*  itm = (int*)(sm + K1_ITM);
    const int tid = threadIdx.x;
    const int warp = tid >> 5, lane = tid & 31;

    const bool is_hq = blockIdx.x < K1_HQ_BLOCKS;
    const int rbase = (is_hq ? blockIdx.x : (blockIdx.x - K1_HQ_BLOCKS)) * 32;
    const float* vecs = is_hq ? cvecs : tvecs;
    const int* items  = is_hq ? citems : titems;
    const int rowsper = is_hq ? WIN : NT;
    const int wcol    = is_hq ? EMB : 0;

    if (tid < 32) {
        int r = rbase + tid;
        itm[tid] = items[(r / rowsper) * rowsper + (r % rowsper)];
    }
    __syncthreads();

    for (int i = tid; i < 32 * 32; i += 256) {
        int row = i >> 5, c = i & 31;
        *(float4*)(X + row * 132 + c * 4) =
            *(const float4*)(vecs + (size_t)itm[row] * EMB + c * 4);
    }

    ull acc[4][2];
#pragma unroll
    for (int r = 0; r < 4; r++) { acc[r][0] = 0ull; acc[r][1] = 0ull; }

    for (int ec = 0; ec < 4; ++ec) {
        __syncthreads();
        for (int i = tid; i < 4096; i += 256) {
            int n = i >> 5, e = i & 31;
            Wc[e * 130 + n] = W_w[n * 256 + wcol + ec * 32 + e];
        }
        __syncthreads();
#pragma unroll
        for (int e4 = 0; e4 < 8; ++e4) {
            float4 xv[4];
#pragma unroll
            for (int r = 0; r < 4; r++)
                xv[r] = *(const float4*)(X + (warp * 4 + r) * 132 + ec * 32 + e4 * 4);
#pragma unroll
            for (int s = 0; s < 4; ++s) {
                int e = e4 * 4 + s;
                ull wa = *(const ull*)(Wc + e * 130 + 2 * lane);
                ull wb = *(const ull*)(Wc + e * 130 + 64 + 2 * lane);
#pragma unroll
                for (int r = 0; r < 4; r++) {
                    float x = (s == 0) ? xv[r].x : (s == 1) ? xv[r].y
                             : (s == 2) ? xv[r].z : xv[r].w;
                    ull xd = pack2(x, x);
                    acc[r][0] = fma2v(xd, wa, acc[r][0]);
                    acc[r][1] = fma2v(xd, wb, acc[r][1]);
                }
            }
        }
    }

    if (is_hq) {
        float2 b0 = *(const float2*)(W_b + 2 * lane);
        float2 b1 = *(const float2*)(W_b + 64 + 2 * lane);
        const int ns0 = lane >> 1, off0 = (lane & 1) * 2;
#pragma unroll
        for (int r = 0; r < 4; r++) {
            int rg = rbase + warp * 4 + r;
            int bb = rg / WIN, ww = rg % WIN;
            float2 a0 = unpack2(acc[r][0]); a0.x += b0.x; a0.y += b0.y;
            float2 a1 = unpack2(acc[r][1]); a1.x += b1.x; a1.y += b1.y;
            float* base = HQT + (size_t)bb * 25600 + ww * 4 + off0;
            *(float2*)(base + ns0 * 800) = a0;
            *(float2*)(base + (16 + ns0) * 800) = a1;
        }
    } else {
#pragma unroll
        for (int r = 0; r < 4; r++) {
            int rg = rbase + warp * 4 + r;
            *(float2*)(HPg + (size_t)rg * EMB + 2 * lane) = unpack2(acc[r][0]);
            *(float2*)(HPg + (size_t)rg * EMB + 64 + 2 * lane) = unpack2(acc[r][1]);
        }
    }
}

// ===================== K2: relu-dot + softmax + AV (single wave) ===========
// grid 1024 = 128 b x 8 t-tiles(8 t); block 128 (4 warps); 8 CTAs/SM
#define K2_SHP   0              /* [8][132] (att) — union with SCR */
#define K2_SCR   0              /* [32][128] AV partials */
#define K2_HW    4096
#define K2_ATT   4224           /* [8][224] */
#define K2_MADD  6016
#define K2_CI    6216
#define K2_MISC  6416           /* [0]=rnorm [1]=mask flag */
#define K2_FLOATS 6424
#define K2_BYTES (K2_FLOATS * 4)

__global__ void __launch_bounds__(128, 8)
att_kernel(const float* __restrict__ cvecs, const float* __restrict__ h_w,
           const int* __restrict__ citems, const unsigned char* __restrict__ mask,
           float* __restrict__ out)
{
    extern __shared__ float sm[];
    float* SHP  = sm + K2_SHP;
    float* SHW  = sm + K2_HW;
    float* ATT  = sm + K2_ATT;
    float* MADD = sm + K2_MADD;
    int*   CI   = (int*)(sm + K2_CI);
    const int tid = threadIdx.x;
    const int b  = blockIdx.x >> 3;
    const int t0 = (blockIdx.x & 7) * 8;
    const int warp = tid >> 5, lane = tid & 31;

    if (tid == 0) ((int*)sm)[K2_MISC + 1] = 0;
    __syncthreads();
    for (int i = tid; i < 200; i += 128) {
        unsigned w32 = ((const unsigned*)mask)[i];
        if (w32 > 1u) ((int*)sm)[K2_MISC + 1] = 1;   // benign race
    }
    __syncthreads();
    {
        const bool bytes_layout = ((int*)sm)[K2_MISC + 1] != 0;
        for (int i = tid; i < 200; i += 128) {
            int mv = bytes_layout ? (int)mask[b * WIN + i]
                                  : ((const int*)mask)[b * WIN + i];
            MADD[i] = mv ? NEG_INF : 0.0f;
            CI[i] = citems[b * WIN + i];
        }
        SHW[tid] = h_w[tid];
    }
    for (int i = tid; i < 8 * 32; i += 128) {
        int t = i >> 5, c = i & 31;
        *(float4*)(SHP + t * 132 + c * 4) =
            *(const float4*)(HPg + ((size_t)(b * NT + t0 + t)) * EMB + c * 4);
    }
    __syncthreads();
    if (tid < 32) {  // rnorm (read after later syncs)
        float c = 0.0f;
        for (int w = tid; w < WIN; w += 32) c += (MADD[w] < 0.0f) ? 1.0f : 0.0f;
#pragma unroll
        for (int o = 16; o; o >>= 1) c += __shfl_xor_sync(0xffffffffu, c, o);
        if (tid == 0) sm[K2_MISC] = 1.0f / sqrtf(1000.0f - c);
    }

    // ---- att: thread owns one w; two w-passes (w=tid, w=128+tid) ----
#pragma unroll
    for (int wp = 0; wp < 2; ++wp) {
        const int w = tid + wp * 128;
        if (w < WIN) {
            const float* hqp = HQT + (size_t)b * 25600 + w * 4;
            ull acc[8];
#pragma unroll
            for (int t = 0; t < 8; ++t) acc[t] = 0ull;
#pragma unroll 2
            for (int ns = 0; ns < 32; ++ns) {
                ulonglong2 hq = *(const ulonglong2*)(hqp + ns * 800);
                ulonglong2 hw = *(const ulonglong2*)(SHW + ns * 4);
#pragma unroll
                for (int t = 0; t < 8; ++t) {
                    ulonglong2 p = *(const ulonglong2*)(SHP + t * 132 + ns * 4);
                    relu_dot2(acc[t], p.x, hq.x, hw.x);
                    relu_dot2(acc[t], p.y, hq.y, hw.y);
                }
            }
#pragma unroll
            for (int t = 0; t < 8; ++t) {
                float2 a = unpack2(acc[t]);
                ATT[t * 224 + w] = a.x + a.y;
            }
        }
    }
    __syncthreads();

    // ---- softmax over w per t (4 warps x 2t) ----
    for (int t = warp; t < 8; t += 4) {
        float v[7], p[7];
        float m = NEG_INF;
#pragma unroll
        for (int k = 0; k < 7; k++) {
            int w = lane + 32 * k;
            v[k] = (w < WIN) ? (ATT[t * 224 + w] + MADD[w]) : NEG_INF;
            m = fmaxf(m, v[k]);
        }
#pragma unroll
        for (int o = 16; o; o >>= 1) m = fmaxf(m, __shfl_xor_sync(0xffffffffu, m, o));
        float s = 0.0f;
#pragma unroll
        for (int k = 0; k < 7; k++) { p[k] = __expf(v[k] - m); s += p[k]; }
#pragma unroll
        for (int o = 16; o; o >>= 1) s += __shfl_xor_sync(0xffffffffu, s, o);
        float inv = 1.0f / s;
#pragma unroll
        for (int k = 0; k < 7; k++) {
            int w = lane + 32 * k;
            if (w < WIN) ATT[t * 224 + w] = p[k] * inv;
        }
    }
    __syncthreads();   // ATT final; SHP dead -> SCR reuse safe

    // ---- AV: warp = w-quarter; 8 t accs; kv from L2; partials in smem ----
    {
        float* SCR = sm + K2_SCR;
        ull acc[8][2];
#pragma unroll
        for (int t8 = 0; t8 < 8; ++t8) { acc[t8][0] = 0ull; acc[t8][1] = 0ull; }
#pragma unroll 2
        for (int wi = 0; wi < 50; ++wi) {
            int w = warp * 50 + wi;
            ulonglong2 kv = *(const ulonglong2*)(cvecs + (size_t)CI[w] * EMB + lane * 4);
#pragma unroll
            for (int t8 = 0; t8 < 8; ++t8) {
                float x = ATT[t8 * 224 + w];   // broadcast
                ull d = pack2(x, x);
                acc[t8][0] = fma2v(d, kv.x, acc[t8][0]);
                acc[t8][1] = fma2v(d, kv.y, acc[t8][1]);
            }
        }
#pragma unroll
        for (int t8 = 0; t8 < 8; ++t8) {
            ulonglong2 v; v.x = acc[t8][0]; v.y = acc[t8][1];
            *(ulonglong2*)(SCR + (size_t)(warp * 8 + t8) * 128 + lane * 4) = v;
        }
    }
    __syncthreads();

    // ---- reduce 4 partials + scale + store ----
    {
        const float rn = sm[K2_MISC];
        for (int i = tid; i < 8 * 128; i += 128) {
            int t = i >> 7, e = i & 127;
            float s = 0.0f;
#pragma unroll
            for (int wg = 0; wg < 4; ++wg)
                s += sm[K2_SCR + (size_t)(wg * 8 + t) * 128 + e];
            out[(size_t)(b * NT + t0 + t) * EMB + e] = s * rn;
        }
    }
}

extern "C" void kernel_launch(void* const* d_in, const int* in_sizes, int n_in,
                              void* d_out, int out_size)
{
    const float* tvecs = (const float*)d_in[0];
    const float* cvecs = (const float*)d_in[1];
    const float* W_w   = (const float*)d_in[2];
    const float* W_b   = (const float*)d_in[3];
    const float* h_w   = (const float*)d_in[4];
    const int*   ti    = (const int*)d_in[6];
    const int*   ci    = (const int*)d_in[7];
    const unsigned char* mask = (const unsigned char*)d_in[8];

    cudaFuncSetAttribute(proj_kernel, cudaFuncAttributeMaxDynamicSharedMemorySize, K1_BYTES);
    cudaFuncSetAttribute(att_kernel,  cudaFuncAttributeMaxDynamicSharedMemorySize, K2_BYTES);
    proj_kernel<<<K1_BLOCKS, 256, K1_BYTES>>>(tvecs, cvecs, W_w, W_b, ti, ci);
    att_kernel<<<B_ * 8, 128, K2_BYTES>>>(cvecs, h_w, ci, mask, (float*)d_out);
}